// round 14
// baseline (speedup 1.0000x reference)
#include <cuda_runtime.h>
#include <cstdint>
#include <math.h>

#define TT 4096
#define DD 1024
#define HH 768
#define EE 23
#define KTOP 3

// ---------------- device scratch (same set as R3, which passed) ----------------
__device__ int   g_cnt[EE];
__device__ float g_psum[EE];
__device__ int   g_tok[EE * TT];
__device__ float g_wt[EE * TT];
__device__ float g_h[(size_t)EE * TT * HH];   // per-expert hidden (padded layout)
__device__ float g_hs[(size_t)TT * HH];       // shared-expert hidden

// ---------------- helpers ----------------
__device__ __forceinline__ void cp16(unsigned s, const void* g) {
    asm volatile("cp.async.cg.shared.global [%0], [%1], 16;" :: "r"(s), "l"(g));
}
__device__ __forceinline__ void cp_commit() { asm volatile("cp.async.commit_group;"); }
template<int N> __device__ __forceinline__ void cp_wait() {
    asm volatile("cp.async.wait_group %0;" :: "n"(N));
}

// ---------------- zero accumulators ----------------
__global__ void zero_k() {
    int i = threadIdx.x;
    if (i < EE) { g_cnt[i] = 0; g_psum[i] = 0.f; }
}

// ---------------- gating (verbatim from R3) ----------------
__global__ __launch_bounds__(736) void gating_k(
    const float* __restrict__ x, const float* __restrict__ gW,
    const float* __restrict__ gb, const float* __restrict__ bias)
{
    int t = blockIdx.x;
    __shared__ float xs[DD];
    __shared__ float sg[EE];
    for (int i = threadIdx.x; i < DD; i += blockDim.x) xs[i] = x[(size_t)t * DD + i];
    __syncthreads();
    int warp = threadIdx.x >> 5, lane = threadIdx.x & 31;
    if (warp < EE) {
        float s = 0.f;
        for (int d = lane; d < DD; d += 32) s += xs[d] * gW[d * EE + warp];
        #pragma unroll
        for (int o = 16; o; o >>= 1) s += __shfl_xor_sync(0xffffffffu, s, o);
        if (lane == 0) sg[warp] = 1.f / (1.f + expf(-(s + gb[warp])));
    }
    __syncthreads();
    if (threadIdx.x == 0) {
        float g[EE]; float sumg = 0.f;
        #pragma unroll
        for (int e = 0; e < EE; e++) { g[e] = sg[e]; sumg += g[e]; }
        int idx[KTOP]; float wv[KTOP];
        bool used[EE];
        #pragma unroll
        for (int e = 0; e < EE; e++) used[e] = false;
        #pragma unroll
        for (int k = 0; k < KTOP; k++) {
            float best = -1e30f; int bi = 0;
            for (int e = 0; e < EE; e++) {
                if (!used[e]) {
                    float v = g[e] + bias[e];
                    if (v > best) { best = v; bi = e; }
                }
            }
            used[bi] = true; idx[k] = bi; wv[k] = g[bi];
        }
        float ws = wv[0] + wv[1] + wv[2];
        #pragma unroll
        for (int k = 0; k < KTOP; k++) {
            int e = idx[k];
            int slot = atomicAdd(&g_cnt[e], 1);
            g_tok[e * TT + slot] = t;
            g_wt[e * TT + slot]  = wv[k] / ws;
        }
        float inv = 1.f / sumg;
        #pragma unroll
        for (int e = 0; e < EE; e++) atomicAdd(&g_psum[e], g[e] * inv);
    }
}

// ---------------- FFN GEMM: all-cp.async double buffer, plain FFMA ----------------
// 128x128 tile, 256 threads, 8x8 acc per thread, BK=16.
// As[st][m][k] row-major (64B rows), Bs[st][k][n].
template<bool MOE, bool FIRST>
__global__ __launch_bounds__(256, 2) void ffn_k(
    const float* __restrict__ x,
    const float* __restrict__ W,
    const float* __restrict__ b,
    float* __restrict__ out)
{
    constexpr int BM = 128, BN = 128, BK = 16;
    constexpr int Kdim = FIRST ? DD : HH;
    constexpr int Ndim = FIRST ? HH : DD;
    constexpr int NT = Kdim / BK;

    const int e   = MOE ? blockIdx.z : 0;
    const int cnt = MOE ? g_cnt[e] : TT;
    const int m0  = blockIdx.y * BM;
    if (m0 >= cnt) return;
    const int n0  = blockIdx.x * BN;
    const int tid = threadIdx.x;

    __shared__ float As[2][BM][BK];
    __shared__ float Bs[2][BK][BN];
    __shared__ int   s_tok[BM];
    __shared__ float s_wt[BM];

    const float* Wexp = MOE ? (W + (size_t)e * Kdim * Ndim) : W;
    const float* bexp = MOE ? (b + (size_t)e * Ndim) : b;

    if (MOE) {
        for (int i = tid; i < BM; i += 256) {
            int m = m0 + i;
            s_tok[i] = (m < cnt) ? g_tok[e * TT + m] : 0;
            s_wt[i]  = (m < cnt) ? g_wt[e * TT + m] : 0.f;
        }
        __syncthreads();
    }

    // loader mapping: A row a_m (0..127), 8 floats at a_k; B row b_k (0..15), 8 floats at b_n
    const int a_m = tid >> 1;
    const int a_k = (tid & 1) * 8;
    const int b_k = tid >> 4;
    const int b_n = (tid & 15) * 8;

    const float* arow;
    if (FIRST) {
        int row = MOE ? s_tok[a_m] : (m0 + a_m);
        arow = x + (size_t)row * DD;
    } else {
        if (MOE) arow = g_h + ((size_t)e * TT + (m0 + a_m)) * HH;
        else     arow = g_hs + (size_t)(m0 + a_m) * HH;
    }
    const float* brow = Wexp + (size_t)b_k * Ndim + n0 + b_n;

    unsigned asd[2], bsd[2];
    asd[0] = (unsigned)__cvta_generic_to_shared(&As[0][a_m][a_k]);
    asd[1] = (unsigned)__cvta_generic_to_shared(&As[1][a_m][a_k]);
    bsd[0] = (unsigned)__cvta_generic_to_shared(&Bs[0][b_k][b_n]);
    bsd[1] = (unsigned)__cvta_generic_to_shared(&Bs[1][b_k][b_n]);

    auto load_chunk = [&](int kt, int st) {
        const float* as = arow + kt * BK + a_k;
        const float* bs = brow + (size_t)kt * BK * Ndim;
        cp16(asd[st],      as);
        cp16(asd[st] + 16, as + 4);
        cp16(bsd[st],      bs);
        cp16(bsd[st] + 16, bs + 4);
        cp_commit();
    };

    const int tx = tid & 15, ty = tid >> 4;

    float acc[8][8];
    #pragma unroll
    for (int i = 0; i < 8; i++)
        #pragma unroll
        for (int j = 0; j < 8; j++) acc[i][j] = 0.f;

    // prologue
    load_chunk(0, 0);
    cp_wait<0>();
    __syncthreads();

    #pragma unroll 1
    for (int kt = 0; kt < NT; kt++) {
        const int cur = kt & 1, nxt = cur ^ 1;
        if (kt + 1 < NT) load_chunk(kt + 1, nxt);

        #pragma unroll
        for (int k4 = 0; k4 < 4; k4++) {
            float a[8][4];
            #pragma unroll
            for (int i = 0; i < 8; i++) {
                float4 v = *(const float4*)&As[cur][ty * 8 + i][k4 * 4];
                a[i][0] = v.x; a[i][1] = v.y; a[i][2] = v.z; a[i][3] = v.w;
            }
            #pragma unroll
            for (int kk = 0; kk < 4; kk++) {
                float4 b0 = *(const float4*)&Bs[cur][k4 * 4 + kk][tx * 8];
                float4 b1 = *(const float4*)&Bs[cur][k4 * 4 + kk][tx * 8 + 4];
                float rb[8] = {b0.x, b0.y, b0.z, b0.w, b1.x, b1.y, b1.z, b1.w};
                #pragma unroll
                for (int i = 0; i < 8; i++)
                    #pragma unroll
                    for (int j = 0; j < 8; j++)
                        acc[i][j] += a[i][kk] * rb[j];
            }
        }

        cp_wait<0>();
        __syncthreads();
    }

    float bb[8];
    #pragma unroll
    for (int j = 0; j < 8; j++) bb[j] = bexp[n0 + tx * 8 + j];

    #pragma unroll
    for (int i = 0; i < 8; i++) {
        int m = m0 + ty * 8 + i;
        if (MOE && m >= cnt) continue;
        #pragma unroll
        for (int j = 0; j < 8; j++) {
            float v = acc[i][j] + bb[j];
            int n = n0 + tx * 8 + j;
            if (FIRST) {
                v = 0.5f * v * (1.f + erff(v * 0.70710678118654752f));
                if (MOE) g_h[((size_t)e * TT + m) * HH + n] = v;
                else     g_hs[(size_t)m * HH + n] = v;
            } else {
                if (MOE) {
                    atomicAdd(&out[(size_t)s_tok[ty * 8 + i] * DD + n],
                              s_wt[ty * 8 + i] * v);
                } else {
                    out[(size_t)m * DD + n] = v;
                }
            }
        }
    }
}

// ---------------- finalize ----------------
__global__ void finalize_k(float* __restrict__ out, int out_size) {
    if (blockIdx.x == 0 && threadIdx.x == 0) {
        float aux = 0.f;
        for (int e = 0; e < EE; e++) {
            float P = g_psum[e] / (float)TT;
            float F = (float)EE * (float)g_cnt[e] / (float)(KTOP * TT);
            aux += P * F;
        }
        const int base = TT * DD;
        if (out_size >= base + 1) out[base] = aux;
        for (int e = 0; e < EE; e++)
            if (out_size >= base + 2 + e) out[base + 1 + e] = (float)g_cnt[e];
    }
}

extern "C" void kernel_launch(void* const* d_in, const int* in_sizes, int n_in,
                              void* d_out, int out_size) {
    const float* x    = (const float*)d_in[0];
    const float* gW   = (const float*)d_in[1];
    const float* gb   = (const float*)d_in[2];
    const float* bias = (const float*)d_in[3];
    const float* W1   = (const float*)d_in[4];
    const float* b1   = (const float*)d_in[5];
    const float* W2   = (const float*)d_in[6];
    const float* b2   = (const float*)d_in[7];
    const float* sW1  = (const float*)d_in[8];
    const float* sb1  = (const float*)d_in[9];
    const float* sW2  = (const float*)d_in[10];
    const float* sb2  = (const float*)d_in[11];
    float* out = (float*)d_out;

    zero_k<<<1, 32>>>();
    gating_k<<<TT, 736>>>(x, gW, gb, bias);

    ffn_k<true, true><<<dim3(HH / 128, TT / 128, EE), 256>>>(x, W1, b1, nullptr);
    ffn_k<false, true><<<dim3(HH / 128, TT / 128, 1), 256>>>(x, sW1, sb1, nullptr);
    ffn_k<false, false><<<dim3(DD / 128, TT / 128, 1), 256>>>(nullptr, sW2, sb2, out);
    ffn_k<true, false><<<dim3(DD / 128, TT / 128, EE), 256>>>(nullptr, W2, b2, out);

    finalize_k<<<1, 32>>>(out, out_size);
}

// round 16
// speedup vs baseline: 1.0794x; 1.0794x over previous
#include <cuda_runtime.h>
#include <cstdint>
#include <math.h>

#define TT 4096
#define DD 1024
#define HH 768
#define EE 23
#define NE (EE + 1)   // experts + virtual shared expert (slice 23)
#define KTOP 3

// ---------------- device scratch (<= R3's passing footprint) ----------------
__device__ int   g_cnt[NE];
__device__ float g_psum[EE];
__device__ int   g_tok[NE * TT];
__device__ float g_wt[NE * TT];
__device__ float g_h[(size_t)NE * TT * HH];   // hidden, padded per slice (~302 MB)

// ---------------- helpers ----------------
__device__ __forceinline__ void cp16(unsigned s, const void* g) {
    asm volatile("cp.async.cg.shared.global [%0], [%1], 16;" :: "r"(s), "l"(g));
}
__device__ __forceinline__ void cp_commit() { asm volatile("cp.async.commit_group;"); }
template<int N> __device__ __forceinline__ void cp_wait() {
    asm volatile("cp.async.wait_group %0;" :: "n"(N));
}

// ---------------- zero / fill ----------------
__global__ void zero_k() {
    int i = threadIdx.x;
    if (i < EE) { g_cnt[i] = 0; g_psum[i] = 0.f; }
    if (i == EE) g_cnt[EE] = TT;
}
__global__ __launch_bounds__(256) void fill23_k() {
    int i = blockIdx.x * 256 + threadIdx.x;
    if (i < TT) { g_tok[EE * TT + i] = i; g_wt[EE * TT + i] = 1.f; }
}
__global__ __launch_bounds__(256) void zero_out_k(float* __restrict__ out, int n4) {
    int i = blockIdx.x * 256 + threadIdx.x;
    if (i < n4) *(float4*)(out + (size_t)i * 4) = make_float4(0.f, 0.f, 0.f, 0.f);
}

// ---------------- gating (verbatim from R3/R14) ----------------
__global__ __launch_bounds__(736) void gating_k(
    const float* __restrict__ x, const float* __restrict__ gW,
    const float* __restrict__ gb, const float* __restrict__ bias)
{
    int t = blockIdx.x;
    __shared__ float xs[DD];
    __shared__ float sg[EE];
    for (int i = threadIdx.x; i < DD; i += blockDim.x) xs[i] = x[(size_t)t * DD + i];
    __syncthreads();
    int warp = threadIdx.x >> 5, lane = threadIdx.x & 31;
    if (warp < EE) {
        float s = 0.f;
        for (int d = lane; d < DD; d += 32) s += xs[d] * gW[d * EE + warp];
        #pragma unroll
        for (int o = 16; o; o >>= 1) s += __shfl_xor_sync(0xffffffffu, s, o);
        if (lane == 0) sg[warp] = 1.f / (1.f + expf(-(s + gb[warp])));
    }
    __syncthreads();
    if (threadIdx.x == 0) {
        float g[EE]; float sumg = 0.f;
        #pragma unroll
        for (int e = 0; e < EE; e++) { g[e] = sg[e]; sumg += g[e]; }
        int idx[KTOP]; float wv[KTOP];
        bool used[EE];
        #pragma unroll
        for (int e = 0; e < EE; e++) used[e] = false;
        #pragma unroll
        for (int k = 0; k < KTOP; k++) {
            float best = -1e30f; int bi = 0;
            for (int e = 0; e < EE; e++) {
                if (!used[e]) {
                    float v = g[e] + bias[e];
                    if (v > best) { best = v; bi = e; }
                }
            }
            used[bi] = true; idx[k] = bi; wv[k] = g[bi];
        }
        float ws = wv[0] + wv[1] + wv[2];
        #pragma unroll
        for (int k = 0; k < KTOP; k++) {
            int e = idx[k];
            int slot = atomicAdd(&g_cnt[e], 1);
            g_tok[e * TT + slot] = t;
            g_wt[e * TT + slot]  = wv[k] / ws;
        }
        float inv = 1.f / sumg;
        #pragma unroll
        for (int e = 0; e < EE; e++) atomicAdd(&g_psum[e], g[e] * inv);
    }
}

// ---------------- unified FFN GEMM (24 slices, slice 23 = shared expert) ----------------
// 128x128 tile, 256 threads, 8x8 acc, BK=16, 2-stage cp.async. Same core as R14.
// blockIdx.x = ncol * NE + e  (slices interleaved across the launch)
template<bool FIRST>
__global__ __launch_bounds__(256, 2) void ffn_k(
    const float* __restrict__ x,
    const float* __restrict__ W,   const float* __restrict__ sW,
    const float* __restrict__ b,   const float* __restrict__ sb,
    float* __restrict__ out)
{
    constexpr int BM = 128, BN = 128, BK = 16;
    constexpr int Kdim = FIRST ? DD : HH;
    constexpr int Ndim = FIRST ? HH : DD;
    constexpr int NT = Kdim / BK;

    const int e   = blockIdx.x % NE;
    const int n0  = (blockIdx.x / NE) * BN;
    const int cnt = g_cnt[e];
    const int m0  = blockIdx.y * BM;
    if (m0 >= cnt) return;
    const int tid = threadIdx.x;

    __shared__ float As[2][BM][BK];
    __shared__ float Bs[2][BK][BN];
    __shared__ int   s_tok[BM];
    __shared__ float s_wt[BM];

    const float* Wexp = (e < EE) ? (W + (size_t)e * Kdim * Ndim) : sW;
    const float* bexp = (e < EE) ? (b + (size_t)e * Ndim) : sb;

    for (int i = tid; i < BM; i += 256) {
        int m = m0 + i;
        s_tok[i] = (m < cnt) ? g_tok[e * TT + m] : 0;
        s_wt[i]  = (m < cnt) ? g_wt[e * TT + m] : 0.f;
    }
    __syncthreads();

    const int a_m = tid >> 1;
    const int a_k = (tid & 1) * 8;
    const int b_k = tid >> 4;
    const int b_n = (tid & 15) * 8;

    const float* arow;
    if (FIRST) {
        arow = x + (size_t)s_tok[a_m] * DD;
    } else {
        arow = g_h + ((size_t)e * TT + (m0 + a_m)) * HH;
    }
    const float* brow = Wexp + (size_t)b_k * Ndim + n0 + b_n;

    unsigned asd[2], bsd[2];
    asd[0] = (unsigned)__cvta_generic_to_shared(&As[0][a_m][a_k]);
    asd[1] = (unsigned)__cvta_generic_to_shared(&As[1][a_m][a_k]);
    bsd[0] = (unsigned)__cvta_generic_to_shared(&Bs[0][b_k][b_n]);
    bsd[1] = (unsigned)__cvta_generic_to_shared(&Bs[1][b_k][b_n]);

    auto load_chunk = [&](int kt, int st) {
        const float* as = arow + kt * BK + a_k;
        const float* bs = brow + (size_t)kt * BK * Ndim;
        cp16(asd[st],      as);
        cp16(asd[st] + 16, as + 4);
        cp16(bsd[st],      bs);
        cp16(bsd[st] + 16, bs + 4);
        cp_commit();
    };

    const int tx = tid & 15, ty = tid >> 4;

    float acc[8][8];
    #pragma unroll
    for (int i = 0; i < 8; i++)
        #pragma unroll
        for (int j = 0; j < 8; j++) acc[i][j] = 0.f;

    load_chunk(0, 0);
    cp_wait<0>();
    __syncthreads();

    #pragma unroll 1
    for (int kt = 0; kt < NT; kt++) {
        const int cur = kt & 1, nxt = cur ^ 1;
        if (kt + 1 < NT) load_chunk(kt + 1, nxt);

        #pragma unroll
        for (int k4 = 0; k4 < 4; k4++) {
            float a[8][4];
            #pragma unroll
            for (int i = 0; i < 8; i++) {
                float4 v = *(const float4*)&As[cur][ty * 8 + i][k4 * 4];
                a[i][0] = v.x; a[i][1] = v.y; a[i][2] = v.z; a[i][3] = v.w;
            }
            #pragma unroll
            for (int kk = 0; kk < 4; kk++) {
                float4 b0 = *(const float4*)&Bs[cur][k4 * 4 + kk][tx * 8];
                float4 b1 = *(const float4*)&Bs[cur][k4 * 4 + kk][tx * 8 + 4];
                float rb[8] = {b0.x, b0.y, b0.z, b0.w, b1.x, b1.y, b1.z, b1.w};
                #pragma unroll
                for (int i = 0; i < 8; i++)
                    #pragma unroll
                    for (int j = 0; j < 8; j++)
                        acc[i][j] += a[i][kk] * rb[j];
            }
        }

        cp_wait<0>();
        __syncthreads();
    }

    float bb[8];
    #pragma unroll
    for (int j = 0; j < 8; j++) bb[j] = bexp[n0 + tx * 8 + j];

    #pragma unroll
    for (int i = 0; i < 8; i++) {
        int m = m0 + ty * 8 + i;
        if (m >= cnt) continue;
        #pragma unroll
        for (int j = 0; j < 8; j++) {
            float v = acc[i][j] + bb[j];
            int n = n0 + tx * 8 + j;
            if (FIRST) {
                v = 0.5f * v * (1.f + erff(v * 0.70710678118654752f));
                g_h[((size_t)e * TT + m) * HH + n] = v;
            } else {
                atomicAdd(&out[(size_t)s_tok[ty * 8 + i] * DD + n],
                          s_wt[ty * 8 + i] * v);
            }
        }
    }
}

// ---------------- finalize ----------------
__global__ void finalize_k(float* __restrict__ out, int out_size) {
    if (blockIdx.x == 0 && threadIdx.x == 0) {
        float aux = 0.f;
        for (int e = 0; e < EE; e++) {
            float P = g_psum[e] / (float)TT;
            float F = (float)EE * (float)g_cnt[e] / (float)(KTOP * TT);
            aux += P * F;
        }
        const int base = TT * DD;
        if (out_size >= base + 1) out[base] = aux;
        for (int e = 0; e < EE; e++)
            if (out_size >= base + 2 + e) out[base + 1 + e] = (float)g_cnt[e];
    }
}

extern "C" void kernel_launch(void* const* d_in, const int* in_sizes, int n_in,
                              void* d_out, int out_size) {
    const float* x    = (const float*)d_in[0];
    const float* gW   = (const float*)d_in[1];
    const float* gb   = (const float*)d_in[2];
    const float* bias = (const float*)d_in[3];
    const float* W1   = (const float*)d_in[4];
    const float* b1   = (const float*)d_in[5];
    const float* W2   = (const float*)d_in[6];
    const float* b2   = (const float*)d_in[7];
    const float* sW1  = (const float*)d_in[8];
    const float* sb1  = (const float*)d_in[9];
    const float* sW2  = (const float*)d_in[10];
    const float* sb2  = (const float*)d_in[11];
    float* out = (float*)d_out;

    zero_k<<<1, 32>>>();
    gating_k<<<TT, 736>>>(x, gW, gb, bias);
    fill23_k<<<(TT + 255) / 256, 256>>>();

    // zero the output (float4 granularity; out_size = TT*DD + tail, tail set by finalize)
    int n4 = (TT * DD) / 4;
    zero_out_k<<<(n4 + 255) / 256, 256>>>(out, n4);

    // fused GEMM1: all 24 slices, interleaved in blockIdx.x
    ffn_k<true ><<<dim3((HH / 128) * NE, TT / 128), 256>>>(x, W1, sW1, b1, sb1, nullptr);
    // fused GEMM2: all 24 slices, all weighted-atomic into zeroed out
    ffn_k<false><<<dim3((DD / 128) * NE, TT / 128), 256>>>(nullptr, W2, sW2, b2, sb2, out);

    finalize_k<<<1, 32>>>(out, out_size);
}